// round 12
// baseline (speedup 1.0000x reference)
#include <cuda_runtime.h>

#define BATCH 64
#define NPTS  8192
#define SGRID 384
#define OUTD  128
#define CELLS (BATCH * OUTD * OUTD)      // 1,048,576 padded cells (float4)

__device__ float4 d_scratch [CELLS];     // 16MB; zeroed by k_compute each call
                                         // (BSS zero-init covers nothing extra)
__device__ int2   d_blockmin[BATCH * 16];
__device__ uint2  d_gpack   [BATCH * NPTS / 2];

// Single 16B vector reduction — sm_90+; 16B-aligned address.
__device__ __forceinline__ void red_add_v4f32(float* p, float a, float b, float c) {
    asm volatile("red.global.add.v4.f32 [%0], {%1, %2, %3, %4};"
                 :: "l"(p), "f"(a), "f"(b), "f"(c), "f"(0.0f) : "memory");
}

// round(e/3) + residual, bit-identical to q=rintf(__fdiv_rn(e,3)); d=e-3q.
// Fast path: multiply by 1/3 (error < 2.5e-5 in quotient units); decisions can
// only differ from the reference double-rounding inside ||d|-1.5| < 1.5e-4,
// so a 5e-4 guard band falling back to the exact reference path is airtight.
__device__ __forceinline__ void div3_round(float e, float& kf, float& d) {
    kf = rintf(e * 0.33333334f);
    d  = fmaf(-3.0f, kf, e);              // exact: 3*kf is an exact integer
    if (fabsf(fabsf(d) - 1.5f) < 5e-4f) { // rare (~0.03% of lanes)
        kf = rintf(__fdiv_rn(e, 3.0f));
        d  = fmaf(-3.0f, kf, e);
    }
}

// ---------------------------------------------------------------------------
// k1: zero scratch + lattice math + per-block coord min.
// 1024 blocks x 256 thr, 2 pts/thread, ~86% occupancy target.
// ---------------------------------------------------------------------------
__global__ void __launch_bounds__(256, 7)
k_compute(const float* __restrict__ pc1, const float* __restrict__ tmat)
{
    // zero scratch: 1,048,576 float4 over 262,144 threads (4 each)
    {
        const int gid = blockIdx.x * 256 + threadIdx.x;
        const float4 z = make_float4(0.f, 0.f, 0.f, 0.f);
        #pragma unroll
        for (int i = 0; i < 4; i++)
            d_scratch[(size_t)i * 262144 + gid] = z;
    }

    const int b    = blockIdx.x >> 4;            // 16 blocks per batch
    const int base = (blockIdx.x & 15) << 9;     // 512 points per block
    const int n0   = base + (threadIdx.x << 1);  // 2 consecutive points

    __shared__ float M[9];
    if (threadIdx.x < 9) M[threadIdx.x] = tmat[b * 9 + threadIdx.x];
    __syncthreads();

    const float* p = pc1 + (size_t)b * 3 * NPTS + n0;
    const float2 P0 = *reinterpret_cast<const float2*>(p);
    const float2 P1 = *reinterpret_cast<const float2*>(p + NPTS);
    const float2 P2 = *reinterpret_cast<const float2*>(p + 2 * NPTS);

    unsigned pk[2];
    int mm0 = 0x7FFFFFFF, mm1 = 0x7FFFFFFF;

    #pragma unroll
    for (int k = 0; k < 2; k++) {
        const float p0 = (&P0.x)[k], p1 = (&P1.x)[k], p2 = (&P2.x)[k];

        const float e0 = M[0] * p0 + M[1] * p1 + M[2] * p2;
        const float e1 = M[3] * p0 + M[4] * p1 + M[5] * p2;
        const float e2 = M[6] * p0 + M[7] * p1 + M[8] * p2;

        float q0, q1, q2, d0, d1, d2;
        div3_round(e0, q0, d0);
        div3_round(e1, q1, d1);
        div3_round(e2, q2, d2);

        const int i0 = (int)q0, i1 = (int)q1, i2 = (int)q2;
        const int rs = i0 + i1 + i2;             // remainder_sum (exact)

        // rank = inverse of stable descending argsort of (d0,d1,d2)
        int rk0 = (d1 > d0) + (d2 > d0);
        int rk1 = (d0 > d1) + (d2 > d1) + (d0 == d1);

        int g0 = 3 * i0;
        int g1 = 3 * i1;

        int sh0 = 0, sh1 = 0;
        if (rs > 0) {
            const int thr = 3 - rs;
            sh0 = (rk0 >= thr) ? -3 : 0;
            sh1 = (rk1 >= thr) ? -3 : 0;
        } else if (rs < 0) {
            sh0 = (rk0 < -rs) ? 3 : 0;
            sh1 = (rk1 < -rs) ? 3 : 0;
        }
        g0 += sh0;  g1 += sh1;
        rk0 += sh0 + rs;
        rk1 += sh1 + rs;

        // JAX gather semantics for CANONICAL[rank]: wrap negatives +3, clamp [0,2]
        int cr0 = (rk0 < 0) ? rk0 + 3 : rk0;  cr0 = min(max(cr0, 0), 2);
        int cr1 = (rk1 < 0) ? rk1 + 3 : rk1;  cr1 = min(max(cr1, 0), 2);

        mm0 = min(mm0, g0 - cr0);   // min_r CANONICAL[cr][r] == -cr
        mm1 = min(mm1, g1 - cr1);

        pk[k] = (unsigned)(g0 + 1024) | ((unsigned)(g1 + 1024) << 16);
    }

    d_gpack[(b * NPTS + n0) >> 1] = make_uint2(pk[0], pk[1]);

    // block min-reduction -> one int2 store
    #pragma unroll
    for (int o = 16; o; o >>= 1) {
        mm0 = min(mm0, __shfl_xor_sync(0xFFFFFFFFu, mm0, o));
        mm1 = min(mm1, __shfl_xor_sync(0xFFFFFFFFu, mm1, o));
    }
    __shared__ int s0[8], s1[8];
    if ((threadIdx.x & 31) == 0) {
        s0[threadIdx.x >> 5] = mm0;
        s1[threadIdx.x >> 5] = mm1;
    }
    __syncthreads();
    if (threadIdx.x == 0) {
        int a = s0[0], c = s1[0];
        #pragma unroll
        for (int w = 1; w < 8; w++) { a = min(a, s0[w]); c = min(c, s1[w]); }
        d_blockmin[blockIdx.x] = make_int2(a, c);
    }
}

// ---------------------------------------------------------------------------
// k2: per-batch offset + one red.v4 per point. 1024 blocks x 256 thr, 2 pts.
// ---------------------------------------------------------------------------
__global__ void __launch_bounds__(256, 7)
k_scatter(const float* __restrict__ feat)
{
    const int b    = blockIdx.x >> 4;
    const int base = (blockIdx.x & 15) << 9;
    const int n0   = base + (threadIdx.x << 1);

    __shared__ int soff0, soff1;
    if (threadIdx.x < 16) {
        int2 v = d_blockmin[(b << 4) + threadIdx.x];
        int a = v.x, c = v.y;
        #pragma unroll
        for (int o = 8; o; o >>= 1) {
            a = min(a, __shfl_xor_sync(0xFFFFu, a, o));
            c = min(c, __shfl_xor_sync(0xFFFFu, c, o));
        }
        if (threadIdx.x == 0) { soff0 = a; soff1 = c; }
    }

    const uint2 PK = d_gpack[(b * NPTS + n0) >> 1];
    const float* f = feat + (size_t)b * 3 * NPTS + n0;
    const float2 F0 = *reinterpret_cast<const float2*>(f);
    const float2 F1 = *reinterpret_cast<const float2*>(f + NPTS);
    const float2 F2 = *reinterpret_cast<const float2*>(f + 2 * NPTS);

    __syncthreads();
    const int off0 = soff0, off1 = soff1;

    #pragma unroll
    for (int k = 0; k < 2; k++) {
        const unsigned pk = (&PK.x)[k];
        const int row = ((int)(pk & 0xFFFFu) - 1024) - off0;   // >= 0
        const int col = ((int)(pk >> 16)     - 1024) - off1;
        if (row < SGRID && col < SGRID) {
            const int u = row / 3;       // row ≡ pts_pick0 (mod 3) exactly
            const int v = col / 3;
            const int idx = (b << 14) + (u << 7) + v;
            red_add_v4f32(&d_scratch[idx].x, (&F0.x)[k], (&F1.x)[k], (&F2.x)[k]);
        }
    }
}

// ---------------------------------------------------------------------------
// k3: compact scratch (16B cells) -> out (12B cells). Pure copy/repack:
// 16MB read + 12.6MB write, no zero-restore (k1 owns zeroing).
// 1024 blocks x 256 threads, block owns 1024 cells / 768 out-float4.
// ---------------------------------------------------------------------------
__global__ void __launch_bounds__(256) k_compact(float* __restrict__ out)
{
    const int cellBase = blockIdx.x << 10;
    float4* o4 = reinterpret_cast<float4*>(out) + ((size_t)blockIdx.x * 768);

    int   q[3], r[3];
    float4 A[3], B[3];
    #pragma unroll
    for (int k = 0; k < 3; k++) {
        q[k] = (k << 8) + threadIdx.x;           // local out-f4 index [0,768)
        const int c0 = (q[k] << 2) / 3;          // local cell [0,1023)
        r[k] = q[k] % 3;
        A[k] = __ldg(&d_scratch[cellBase + c0]);
        B[k] = __ldg(&d_scratch[cellBase + c0 + 1]);
    }
    #pragma unroll
    for (int k = 0; k < 3; k++) {
        float4 v;                                 // window (A.xyz B.xyz)[r, r+4)
        v.x = (r[k] == 0) ? A[k].x : ((r[k] == 1) ? A[k].y : A[k].z);
        v.y = (r[k] == 0) ? A[k].y : ((r[k] == 1) ? A[k].z : B[k].x);
        v.z = (r[k] == 0) ? A[k].z : ((r[k] == 1) ? B[k].x : B[k].y);
        v.w = (r[k] == 0) ? B[k].x : ((r[k] == 1) ? B[k].y : B[k].z);
        o4[q[k]] = v;
    }
}

// ---------------------------------------------------------------------------
extern "C" void kernel_launch(void* const* d_in, const int* in_sizes, int n_in,
                              void* d_out, int out_size)
{
    const float* pc1  = (const float*)d_in[0];
    const float* feat = (const float*)d_in[1];
    const float* tmat = (const float*)d_in[2];
    float*       out  = (float*)d_out;

    k_compute<<<1024, 256>>>(pc1, tmat);
    k_scatter<<<1024, 256>>>(feat);
    k_compact<<<1024, 256>>>(out);
}